// round 12
// baseline (speedup 1.0000x reference)
#include <cuda_runtime.h>
#include <cuda_fp16.h>
#include <math.h>
#include <stdint.h>

#define NB 64
#define NT 4096
#define HE 512
#define HD 512
#define NA 256
#define TCH 64

// ---- scores GEMM tiling ----
#define BM 128
#define BN 256
#define BK 32
#define NKCH (HE / BK)        // 16
#define THREADS 256
#define STAGES 3

// smem tile rows: 64B data + 16B pad = 80B stride
#define ROWB 80
#define ASZ (BM * ROWB)            // 10240
#define BSZ (BN * ROWB)            // 20480
#define BUFSZ (ASZ + BSZ)          // 30720
#define SCAL (STAGES * BUFSZ)      // 92160
#define SMEM_BYTES (SCAL + 1024 + 1024 + 2048)

// ---------------- static device scratch (allocation-free) ----------------
__device__ float g_dec_proj[NB * NA];
__device__ float g_scores[NB * NT];
__device__ float g_ctx_part[NB * TCH * HE];
// fp16 copy of encoder_outputs, written by k_scores, read by k_ctx_part
__device__ __half g_enc16[(size_t)NB * NT * HE];
// prepacked W_enc fp16: [kchunk 16][n 256][k 32] (64B rows)
__device__ unsigned char g_Bs[NKCH * BN * 64];

// ---------------- helpers ----------------
__device__ __forceinline__ unsigned smem_u32(const void* p) {
    unsigned r;
    asm("{ .reg .u64 t; cvta.to.shared.u64 t, %1; cvt.u32.u64 %0, t; }"
        : "=r"(r) : "l"(p));
    return r;
}
__device__ __forceinline__ void cpasync16(unsigned dst, const void* src) {
    asm volatile("cp.async.cg.shared.global [%0], [%1], 16;"
                 :: "r"(dst), "l"(__cvta_generic_to_global(src)) : "memory");
}
__device__ __forceinline__ unsigned pack_h2(float a, float b) {
    __half2 h = __floats2half2_rn(a, b);
    return *reinterpret_cast<unsigned*>(&h);
}

#define LDSM4(r, addr)                                                        \
    asm volatile("ldmatrix.sync.aligned.m8n8.x4.shared.b16 {%0,%1,%2,%3}, [%4];" \
                 : "=r"((r)[0]), "=r"((r)[1]), "=r"((r)[2]), "=r"((r)[3])     \
                 : "r"(addr))

#define MMA(d, a, b0, b1)                                                     \
    asm volatile(                                                             \
        "mma.sync.aligned.m16n8k16.row.col.f32.f16.f16.f32 "                  \
        "{%0,%1,%2,%3}, {%4,%5,%6,%7}, {%8,%9}, {%0,%1,%2,%3};"               \
        : "+f"((d)[0]), "+f"((d)[1]), "+f"((d)[2]), "+f"((d)[3])              \
        : "r"((a)[0]), "r"((a)[1]), "r"((a)[2]), "r"((a)[3]), "r"(b0), "r"(b1))

// HW tanh approximation (sm_75+, single MUFU op)
__device__ __forceinline__ float ftanh(float x) {
    float r;
    asm("tanh.approx.f32 %0, %1;" : "=f"(r) : "f"(x));
    return r;
}

// ---------------------------------------------------------------------------
// Kernel 0: merged prep. Blocks 0..15: prepack W_enc chunk c=bid.
//           Blocks 16..79: dec_proj for b = bid-16.
// ---------------------------------------------------------------------------
__global__ void k_prep(const float* __restrict__ We,
                       const float* __restrict__ dec,
                       const float* __restrict__ Wd) {
    if (blockIdx.x < NKCH) {
        int c = blockIdx.x;
        int n = threadIdx.x;     // 0..255
        const float* src = We + (size_t)n * HE + c * BK;
        unsigned hbuf[16];
#pragma unroll
        for (int q = 0; q < 8; q++) {
            float4 f = *(const float4*)(src + q * 4);
            hbuf[q * 2 + 0] = pack_h2(f.x, f.y);
            hbuf[q * 2 + 1] = pack_h2(f.z, f.w);
        }
        unsigned char* dsth = g_Bs + ((size_t)c * BN + n) * 64;
#pragma unroll
        for (int q = 0; q < 4; q++)
            ((uint4*)dsth)[q] = make_uint4(hbuf[q*4], hbuf[q*4+1],
                                           hbuf[q*4+2], hbuf[q*4+3]);
    } else {
        int b = blockIdx.x - NKCH;
        int a = threadIdx.x;
        const float4* dp = (const float4*)(dec + (size_t)b * HD);
        const float4* wp = (const float4*)(Wd + (size_t)a * HD);
        float s = 0.f;
#pragma unroll 8
        for (int k = 0; k < HD / 4; ++k) {
            float4 d4 = dp[k];
            float4 w4 = wp[k];
            s += d4.x * w4.x + d4.y * w4.y + d4.z * w4.z + d4.w * w4.w;
        }
        g_dec_proj[b * NA + a] = s;
    }
}

// ---------------------------------------------------------------------------
// Kernel 2: fused scores, mma.sync fp16, depth-3 cp.async pipeline.
//   grid (NT/128, NB), 256 threads, 8 warps (2 M x 4 N), warp tile 64x64.
//   Warp tile widened in M to halve redundant B-fragment LDSM traffic.
// ---------------------------------------------------------------------------
__global__ __launch_bounds__(THREADS, 1)
void k_scores(const float* __restrict__ enc, const float* __restrict__ v) {
    extern __shared__ __align__(128) unsigned char smp[];
    const unsigned sb = smem_u32(smp);

    const int tid = threadIdx.x;
    const int wid = tid >> 5;
    const int l   = tid & 31;
    const int wm  = wid & 1;   // M blocks of 64
    const int wn  = wid >> 1;  // N blocks of 64
    const int b   = blockIdx.y;
    const int t0  = blockIdx.x * BM;

    float* sdec = (float*)(smp + SCAL);
    float* sv   = (float*)(smp + SCAL + 1024);
    float* srow = (float*)(smp + SCAL + 2048);   // [128][4]
    if (tid < NA) {
        sdec[tid] = g_dec_proj[b * NA + tid];
        sv[tid]   = v[tid];
    }

    const float* Abase = enc + ((size_t)b * NT + t0) * HE;
    const int arow = tid >> 1;          // 0..127
    const int aseg = tid & 1;           // 16 floats each

    auto ldA = [&](int c, float4* w) {
        const float* p = Abase + (size_t)arow * HE + c * BK + aseg * 16;
        w[0] = *(const float4*)p;
        w[1] = *(const float4*)(p + 4);
        w[2] = *(const float4*)(p + 8);
        w[3] = *(const float4*)(p + 12);
    };
    auto stA = [&](int st, int c, const float4* w) {
        unsigned off = st * BUFSZ + arow * ROWB + aseg * 32;
        uint4 h0 = make_uint4(pack_h2(w[0].x, w[0].y), pack_h2(w[0].z, w[0].w),
                              pack_h2(w[1].x, w[1].y), pack_h2(w[1].z, w[1].w));
        uint4 h1 = make_uint4(pack_h2(w[2].x, w[2].y), pack_h2(w[2].z, w[2].w),
                              pack_h2(w[3].x, w[3].y), pack_h2(w[3].z, w[3].w));
        *(uint4*)(smp + off)      = h0;
        *(uint4*)(smp + off + 16) = h1;
        __half* g = g_enc16 + ((size_t)b * NT + t0 + arow) * HE + c * BK + aseg * 16;
        *(uint4*)g       = h0;
        *(uint4*)(g + 8) = h1;
    };
    auto ldB = [&](int c, int st) {
#pragma unroll
        for (int it = 0; it < 4; it++) {
            int i   = tid + it * THREADS;   // 0..1023
            int row = i >> 2;
            int cc  = i & 3;
            unsigned dst = sb + st * BUFSZ + ASZ + row * ROWB + cc * 16;
            const unsigned char* src = g_Bs + ((size_t)c * BN + row) * 64 + cc * 16;
            cpasync16(dst, src);
        }
        asm volatile("cp.async.commit_group;" ::: "memory");
    };

    float acc[4][8][4];
#pragma unroll
    for (int i = 0; i < 4; i++)
#pragma unroll
        for (int j = 0; j < 8; j++)
#pragma unroll
            for (int k = 0; k < 4; k++) acc[i][j][k] = 0.f;

    const unsigned a_lane = (wm * 64 + (l & 15)) * ROWB + ((l >> 4) << 4);
    const unsigned b_lane = (wn * 64 + ((l >> 4) & 1) * 8 + (l & 7)) * ROWB
                          + (((l >> 3) & 1) << 4);

    // ---- prologue: stages 0 and 1 ----
    {
        float4 w0[4], w1[4];
        ldA(0, w0);
        ldA(1, w1);
        ldB(0, 0);
        ldB(1, 1);
        stA(0, 0, w0);
        stA(1, 1, w1);
    }
    asm volatile("cp.async.wait_group 1;" ::: "memory");
    __syncthreads();

    for (int c = 0; c < NKCH; c++) {
        const int st = c % STAGES;

        float4 w[4];
        const bool more = (c + 2 < NKCH);
        if (more) {
            ldA(c + 2, w);
            ldB(c + 2, (c + 2) % STAGES);
        }

        const unsigned sA = sb + st * BUFSZ;
        const unsigned sB = sb + st * BUFSZ + ASZ;
#pragma unroll
        for (int k16 = 0; k16 < 2; k16++) {
            unsigned ah[4][4];
            const unsigned aoff = a_lane + k16 * 32;
#pragma unroll
            for (int mf = 0; mf < 4; mf++)
                LDSM4(ah[mf], sA + aoff + mf * (16 * ROWB));
            const unsigned boff = b_lane + k16 * 32;
#pragma unroll
            for (int np = 0; np < 4; np++) {
                unsigned bh[4];
                LDSM4(bh, sB + boff + np * (16 * ROWB));
#pragma unroll
                for (int mf = 0; mf < 4; mf++) {
                    MMA(acc[mf][2 * np],     ah[mf], bh[0], bh[1]);
                    MMA(acc[mf][2 * np + 1], ah[mf], bh[2], bh[3]);
                }
            }
        }

        if (more) {
            stA((c + 2) % STAGES, c + 2, w);
            asm volatile("cp.async.wait_group 1;" ::: "memory");
        } else if (c + 1 < NKCH) {
            asm volatile("cp.async.wait_group 0;" ::: "memory");
        }
        __syncthreads();
    }

    // epilogue: tanh(acc + dec) * v, reduce over 256 cols
    const int gid = l >> 2;
    const int tig = l & 3;
    float rs[4][2];
#pragma unroll
    for (int mf = 0; mf < 4; mf++) { rs[mf][0] = 0.f; rs[mf][1] = 0.f; }
#pragma unroll
    for (int mf = 0; mf < 4; mf++) {
#pragma unroll
        for (int nt = 0; nt < 8; nt++) {
            int col0 = wn * 64 + nt * 8 + tig * 2;
            float d0 = sdec[col0], d1 = sdec[col0 + 1];
            float v0 = sv[col0],   v1 = sv[col0 + 1];
            rs[mf][0] += ftanh(acc[mf][nt][0] + d0) * v0;
            rs[mf][0] += ftanh(acc[mf][nt][1] + d1) * v1;
            rs[mf][1] += ftanh(acc[mf][nt][2] + d0) * v0;
            rs[mf][1] += ftanh(acc[mf][nt][3] + d1) * v1;
        }
    }
#pragma unroll
    for (int mf = 0; mf < 4; mf++)
#pragma unroll
        for (int rh = 0; rh < 2; rh++) {
            float s = rs[mf][rh];
            s += __shfl_xor_sync(0xFFFFFFFFu, s, 1);
            s += __shfl_xor_sync(0xFFFFFFFFu, s, 2);
            if (tig == 0) {
                int row = wm * 64 + mf * 16 + rh * 8 + gid;
                srow[row * 4 + wn] = s;
            }
        }
    __syncthreads();
    if (tid < BM) {
        float s = srow[tid * 4 + 0] + srow[tid * 4 + 1]
                + srow[tid * 4 + 2] + srow[tid * 4 + 3];
        g_scores[(size_t)b * NT + t0 + tid] = s;
    }
}

// ---------------------------------------------------------------------------
// Kernel 3: softmax over T per batch (512 threads, float4)
// ---------------------------------------------------------------------------
__global__ void k_softmax(float* __restrict__ wout) {
    const int b = blockIdx.x;
    const int tid = threadIdx.x;   // 0..511
    __shared__ float sm[512];
    const float4* s4 = (const float4*)(g_scores + (size_t)b * NT);

    float4 x0 = s4[tid];
    float4 x1 = s4[tid + 512];
    float m = fmaxf(fmaxf(fmaxf(x0.x, x0.y), fmaxf(x0.z, x0.w)),
                    fmaxf(fmaxf(x1.x, x1.y), fmaxf(x1.z, x1.w)));
    sm[tid] = m;
    __syncthreads();
    for (int off = 256; off > 0; off >>= 1) {
        if (tid < off) sm[tid] = fmaxf(sm[tid], sm[tid + off]);
        __syncthreads();
    }
    m = sm[0];
    __syncthreads();

    float4 e0, e1;
    e0.x = expf(x0.x - m); e0.y = expf(x0.y - m);
    e0.z = expf(x0.z - m); e0.w = expf(x0.w - m);
    e1.x = expf(x1.x - m); e1.y = expf(x1.y - m);
    e1.z = expf(x1.z - m); e1.w = expf(x1.w - m);
    float z = (e0.x + e0.y) + (e0.z + e0.w) + (e1.x + e1.y) + (e1.z + e1.w);
    sm[tid] = z;
    __syncthreads();
    for (int off = 256; off > 0; off >>= 1) {
        if (tid < off) sm[tid] += sm[tid + off];
        __syncthreads();
    }
    float inv = 1.f / sm[0];

    float4* w4 = (float4*)(wout + (size_t)b * NT);
    e0.x *= inv; e0.y *= inv; e0.z *= inv; e0.w *= inv;
    e1.x *= inv; e1.y *= inv; e1.z *= inv; e1.w *= inv;
    w4[tid]       = e0;
    w4[tid + 512] = e1;
}

// ---------------------------------------------------------------------------
// Kernel 4: context partial sums from fp16 enc copy.
//   grid (NB, TCH), 64 threads; each thread owns 8 columns (16B loads).
// ---------------------------------------------------------------------------
__global__ void k_ctx_part(const float* __restrict__ w) {
    const int b   = blockIdx.x;
    const int tc  = blockIdx.y;
    const int tid = threadIdx.x;   // 0..63
    const int TLEN = NT / TCH;     // 64
    const float*  wp = w + (size_t)b * NT + (size_t)tc * TLEN;
    const __half* ep = g_enc16 + ((size_t)b * NT + (size_t)tc * TLEN) * HE;

    float acc[8];
#pragma unroll
    for (int j = 0; j < 8; j++) acc[j] = 0.f;

#pragma unroll 4
    for (int t = 0; t < TLEN; ++t) {
        float wt = wp[t];
        uint4 hv = *(const uint4*)(ep + (size_t)t * HE + tid * 8);
        const __half2* hp = (const __half2*)&hv;
#pragma unroll
        for (int j = 0; j < 4; j++) {
            float2 f = __half22float2(hp[j]);
            acc[2 * j + 0] = fmaf(wt, f.x, acc[2 * j + 0]);
            acc[2 * j + 1] = fmaf(wt, f.y, acc[2 * j + 1]);
        }
    }
    float* dst = g_ctx_part + ((size_t)b * TCH + tc) * HE + tid * 8;
    *(float4*)dst       = make_float4(acc[0], acc[1], acc[2], acc[3]);
    *(float4*)(dst + 4) = make_float4(acc[4], acc[5], acc[6], acc[7]);
}

// ---------------------------------------------------------------------------
// Kernel 5: reduce partials -> context output.
// ---------------------------------------------------------------------------
__global__ void k_ctx_reduce(float* __restrict__ ctx) {
    int idx = blockIdx.x * blockDim.x + threadIdx.x;
    int b = idx / HE;
    int e = idx % HE;
    float s = 0.f;
#pragma unroll
    for (int c = 0; c < TCH; c++)
        s += g_ctx_part[((size_t)b * TCH + c) * HE + e];
    ctx[idx] = s;
}

// ---------------------------------------------------------------------------
extern "C" void kernel_launch(void* const* d_in, const int* in_sizes, int n_in,
                              void* d_out, int out_size) {
    const float* dec = (const float*)d_in[0];  // (B, H_dec)
    const float* enc = (const float*)d_in[1];  // (B, T, H_enc)
    const float* We  = (const float*)d_in[2];  // (A, H_enc)
    const float* Wd  = (const float*)d_in[3];  // (A, H_dec)
    const float* v   = (const float*)d_in[4];  // (1, A)

    float* out = (float*)d_out;
    float* ctx = out;              // context: B*HE
    float* wts = out + NB * HE;    // attn_weights: B*NT

    cudaFuncSetAttribute(k_scores, cudaFuncAttributeMaxDynamicSharedMemorySize,
                         SMEM_BYTES);

    k_prep<<<NKCH + NB, 256>>>(We, dec, Wd);

    dim3 g2(NT / BM, NB);
    k_scores<<<g2, THREADS, SMEM_BYTES>>>(enc, v);

    k_softmax<<<NB, 512>>>(wts);

    dim3 g4(NB, TCH);
    k_ctx_part<<<g4, 64>>>(wts);

    k_ctx_reduce<<<(NB * HE) / 256, 256>>>(ctx);
}

// round 13
// speedup vs baseline: 1.2668x; 1.2668x over previous
#include <cuda_runtime.h>
#include <cuda_fp16.h>
#include <math.h>
#include <stdint.h>

#define NB 64
#define NT 4096
#define HE 512
#define HD 512
#define NA 256
#define TCH 64

// ---- scores GEMM tiling ----
#define BM 128
#define BN 256
#define BK 32
#define NKCH (HE / BK)        // 16
#define THREADS 512
#define STAGES 3

// smem tile rows: 64B data + 16B pad = 80B stride
#define ROWB 80
#define ASZ (BM * ROWB)            // 10240
#define BSZ (BN * ROWB)            // 20480
#define BUFSZ (ASZ + BSZ)          // 30720
#define SCAL (STAGES * BUFSZ)      // 92160
#define SMEM_BYTES (SCAL + 1024 + 1024 + 2048)

// ---------------- static device scratch (allocation-free) ----------------
__device__ float g_dec_proj[NB * NA];
__device__ float g_scores[NB * NT];
__device__ float g_ctx_part[NB * TCH * HE];
// fp16 copy of encoder_outputs, written by k_scores, read by k_ctx_part
__device__ __half g_enc16[(size_t)NB * NT * HE];
// prepacked W_enc fp16: [kchunk 16][n 256][k 32] (64B rows)
__device__ unsigned char g_Bs[NKCH * BN * 64];

// ---------------- helpers ----------------
__device__ __forceinline__ unsigned smem_u32(const void* p) {
    unsigned r;
    asm("{ .reg .u64 t; cvta.to.shared.u64 t, %1; cvt.u32.u64 %0, t; }"
        : "=r"(r) : "l"(p));
    return r;
}
__device__ __forceinline__ void cpasync16(unsigned dst, const void* src) {
    asm volatile("cp.async.cg.shared.global [%0], [%1], 16;"
                 :: "r"(dst), "l"(__cvta_generic_to_global(src)) : "memory");
}
__device__ __forceinline__ unsigned pack_h2(float a, float b) {
    __half2 h = __floats2half2_rn(a, b);
    return *reinterpret_cast<unsigned*>(&h);
}

#define LDSM4(r, addr)                                                        \
    asm volatile("ldmatrix.sync.aligned.m8n8.x4.shared.b16 {%0,%1,%2,%3}, [%4];" \
                 : "=r"((r)[0]), "=r"((r)[1]), "=r"((r)[2]), "=r"((r)[3])     \
                 : "r"(addr))

#define MMA(d, a, b0, b1)                                                     \
    asm volatile(                                                             \
        "mma.sync.aligned.m16n8k16.row.col.f32.f16.f16.f32 "                  \
        "{%0,%1,%2,%3}, {%4,%5,%6,%7}, {%8,%9}, {%0,%1,%2,%3};"               \
        : "+f"((d)[0]), "+f"((d)[1]), "+f"((d)[2]), "+f"((d)[3])              \
        : "r"((a)[0]), "r"((a)[1]), "r"((a)[2]), "r"((a)[3]), "r"(b0), "r"(b1))

// HW tanh approximation (sm_75+, single MUFU op)
__device__ __forceinline__ float ftanh(float x) {
    float r;
    asm("tanh.approx.f32 %0, %1;" : "=f"(r) : "f"(x));
    return r;
}

// ---------------------------------------------------------------------------
// Kernel 0: prepack W_enc fp16 chunks [c][n][k32]
// ---------------------------------------------------------------------------
__global__ void k_wprep(const float* __restrict__ We) {
    int c = blockIdx.x;      // 0..15
    int n = threadIdx.x;     // 0..255
    const float* src = We + (size_t)n * HE + c * BK;
    unsigned hbuf[16];
#pragma unroll
    for (int q = 0; q < 8; q++) {
        float4 f = *(const float4*)(src + q * 4);
        hbuf[q * 2 + 0] = pack_h2(f.x, f.y);
        hbuf[q * 2 + 1] = pack_h2(f.z, f.w);
    }
    unsigned char* dsth = g_Bs + ((size_t)c * BN + n) * 64;
#pragma unroll
    for (int q = 0; q < 4; q++)
        ((uint4*)dsth)[q] = make_uint4(hbuf[q*4], hbuf[q*4+1], hbuf[q*4+2], hbuf[q*4+3]);
}

// ---------------------------------------------------------------------------
// Kernel 1: dec_proj
// ---------------------------------------------------------------------------
__global__ void k_dec_proj(const float* __restrict__ dec,
                           const float* __restrict__ Wd) {
    int b = blockIdx.x;
    int a = threadIdx.x;
    const float4* dp = (const float4*)(dec + (size_t)b * HD);
    const float4* wp = (const float4*)(Wd + (size_t)a * HD);
    float s = 0.f;
#pragma unroll 8
    for (int k = 0; k < HD / 4; ++k) {
        float4 d4 = dp[k];
        float4 w4 = wp[k];
        s += d4.x * w4.x + d4.y * w4.y + d4.z * w4.z + d4.w * w4.w;
    }
    g_dec_proj[b * NA + a] = s;
}

// ---------------------------------------------------------------------------
// Kernel 2: fused scores, mma.sync fp16, depth-3 cp.async pipeline,
//   frag-level software pipelining. Also side-writes fp16 enc for ctx.
//   grid (NT/128, NB), 512 threads, 16 warps (4 M x 4 N).
// ---------------------------------------------------------------------------
__global__ __launch_bounds__(THREADS, 1)
void k_scores(const float* __restrict__ enc, const float* __restrict__ v) {
    extern __shared__ __align__(128) unsigned char smp[];
    const unsigned sb = smem_u32(smp);

    const int tid = threadIdx.x;
    const int wid = tid >> 5;
    const int l   = tid & 31;
    const int wm  = wid & 3;   // M blocks of 32
    const int wn  = wid >> 2;  // N blocks of 64
    const int b   = blockIdx.y;
    const int t0  = blockIdx.x * BM;

    float* sdec = (float*)(smp + SCAL);
    float* sv   = (float*)(smp + SCAL + 1024);
    float* srow = (float*)(smp + SCAL + 2048);   // [128][4]
    if (tid < NA) {
        sdec[tid] = g_dec_proj[b * NA + tid];
        sv[tid]   = v[tid];
    }

    const float* Abase = enc + ((size_t)b * NT + t0) * HE;
    const int arow = tid >> 2;   // 0..127
    const int aseg = tid & 3;    // 8 floats each

    auto ldA = [&](int c, float4& v0, float4& v1) {
        const float* p = Abase + (size_t)arow * HE + c * BK + aseg * 8;
        v0 = *(const float4*)p;
        v1 = *(const float4*)(p + 4);
    };
    auto stA = [&](int st, int c, float4 v0, float4 v1) {
        unsigned off = st * BUFSZ + arow * ROWB + aseg * 16;
        uint4 h = make_uint4(pack_h2(v0.x, v0.y), pack_h2(v0.z, v0.w),
                             pack_h2(v1.x, v1.y), pack_h2(v1.z, v1.w));
        *(uint4*)(smp + off) = h;
        // side-write fp16 enc copy for the context kernel
        *(uint4*)(g_enc16 + ((size_t)b * NT + t0 + arow) * HE + c * BK + aseg * 8) = h;
    };
    auto ldB = [&](int c, int st) {
#pragma unroll
        for (int it = 0; it < 2; it++) {
            int i   = tid + it * THREADS;   // 0..1023
            int row = i >> 2;
            int cc  = i & 3;
            unsigned dst = sb + st * BUFSZ + ASZ + row * ROWB + cc * 16;
            const unsigned char* src = g_Bs + ((size_t)c * BN + row) * 64 + cc * 16;
            cpasync16(dst, src);
        }
        asm volatile("cp.async.commit_group;" ::: "memory");
    };

    float acc[2][8][4];
#pragma unroll
    for (int i = 0; i < 2; i++)
#pragma unroll
        for (int j = 0; j < 8; j++)
#pragma unroll
            for (int k = 0; k < 4; k++) acc[i][j][k] = 0.f;

    const unsigned a_lane = (wm * 32 + (l & 15)) * ROWB + ((l >> 4) << 4);
    const unsigned b_lane = (wn * 64 + ((l >> 4) & 1) * 8 + (l & 7)) * ROWB
                          + (((l >> 3) & 1) << 4);

    // ---- prologue: stages 0 and 1 ----
    {
        float4 a00, a01, a10, a11;
        ldA(0, a00, a01);
        ldA(1, a10, a11);
        ldB(0, 0);
        ldB(1, 1);
        stA(0, 0, a00, a01);
        stA(1, 1, a10, a11);
    }
    asm volatile("cp.async.wait_group 1;" ::: "memory");
    __syncthreads();

    for (int c = 0; c < NKCH; c++) {
        const int st = c % STAGES;

        float4 w0, w1;
        const bool more = (c + 2 < NKCH);
        if (more) {
            ldA(c + 2, w0, w1);
            ldB(c + 2, (c + 2) % STAGES);
        }

        // ---- compute chunk c with frag-level pipelining ----
        const unsigned sA = sb + st * BUFSZ;
        const unsigned sB = sb + st * BUFSZ + ASZ;
        unsigned ah[2][2][4];   // [k16][mt][frag]
        unsigned bh[2][4];      // double buffer over np
        LDSM4(ah[0][0], sA + a_lane);
        LDSM4(ah[0][1], sA + a_lane + 16 * ROWB);
#pragma unroll
        for (int k16 = 0; k16 < 2; k16++) {
            const unsigned boff = b_lane + k16 * 32;
            LDSM4(bh[0], sB + boff);
            if (k16 == 0) {  // prefetch A frags for k16=1 under np-loop MMAs
                LDSM4(ah[1][0], sA + a_lane + 32);
                LDSM4(ah[1][1], sA + a_lane + 32 + 16 * ROWB);
            }
#pragma unroll
            for (int np = 0; np < 4; np++) {
                if (np < 3)
                    LDSM4(bh[(np + 1) & 1], sB + boff + (np + 1) * (16 * ROWB));
                const unsigned* bc = bh[np & 1];
                MMA(acc[0][2 * np],     ah[k16][0], bc[0], bc[1]);
                MMA(acc[0][2 * np + 1], ah[k16][0], bc[2], bc[3]);
                MMA(acc[1][2 * np],     ah[k16][1], bc[0], bc[1]);
                MMA(acc[1][2 * np + 1], ah[k16][1], bc[2], bc[3]);
            }
        }

        if (more) {
            stA((c + 2) % STAGES, c + 2, w0, w1);
            asm volatile("cp.async.wait_group 1;" ::: "memory");
        } else if (c + 1 < NKCH) {
            asm volatile("cp.async.wait_group 0;" ::: "memory");
        }
        __syncthreads();
    }

    // epilogue: tanh(acc + dec) * v, reduce over 256 cols
    const int gid = l >> 2;
    const int tig = l & 3;
    float rs[2][2] = {{0.f, 0.f}, {0.f, 0.f}};
#pragma unroll
    for (int mt = 0; mt < 2; mt++) {
#pragma unroll
        for (int nt = 0; nt < 8; nt++) {
            int col0 = wn * 64 + nt * 8 + tig * 2;
            float d0 = sdec[col0], d1 = sdec[col0 + 1];
            float v0 = sv[col0],   v1 = sv[col0 + 1];
            rs[mt][0] += ftanh(acc[mt][nt][0] + d0) * v0;
            rs[mt][0] += ftanh(acc[mt][nt][1] + d1) * v1;
            rs[mt][1] += ftanh(acc[mt][nt][2] + d0) * v0;
            rs[mt][1] += ftanh(acc[mt][nt][3] + d1) * v1;
        }
    }
#pragma unroll
    for (int mt = 0; mt < 2; mt++)
#pragma unroll
        for (int rh = 0; rh < 2; rh++) {
            float s = rs[mt][rh];
            s += __shfl_xor_sync(0xFFFFFFFFu, s, 1);
            s += __shfl_xor_sync(0xFFFFFFFFu, s, 2);
            if (tig == 0) {
                int row = wm * 32 + mt * 16 + rh * 8 + gid;
                srow[row * 4 + wn] = s;
            }
        }
    __syncthreads();
    if (tid < BM) {
        float s = srow[tid * 4 + 0] + srow[tid * 4 + 1]
                + srow[tid * 4 + 2] + srow[tid * 4 + 3];
        g_scores[(size_t)b * NT + t0 + tid] = s;
    }
}

// ---------------------------------------------------------------------------
// Kernel 3: softmax over T per batch (512 threads, float4)
// ---------------------------------------------------------------------------
__global__ void k_softmax(float* __restrict__ wout) {
    const int b = blockIdx.x;
    const int tid = threadIdx.x;   // 0..511
    __shared__ float sm[512];
    const float4* s4 = (const float4*)(g_scores + (size_t)b * NT);

    float4 x0 = s4[tid];
    float4 x1 = s4[tid + 512];
    float m = fmaxf(fmaxf(fmaxf(x0.x, x0.y), fmaxf(x0.z, x0.w)),
                    fmaxf(fmaxf(x1.x, x1.y), fmaxf(x1.z, x1.w)));
    sm[tid] = m;
    __syncthreads();
    for (int off = 256; off > 0; off >>= 1) {
        if (tid < off) sm[tid] = fmaxf(sm[tid], sm[tid + off]);
        __syncthreads();
    }
    m = sm[0];
    __syncthreads();

    float4 e0, e1;
    e0.x = expf(x0.x - m); e0.y = expf(x0.y - m);
    e0.z = expf(x0.z - m); e0.w = expf(x0.w - m);
    e1.x = expf(x1.x - m); e1.y = expf(x1.y - m);
    e1.z = expf(x1.z - m); e1.w = expf(x1.w - m);
    float z = (e0.x + e0.y) + (e0.z + e0.w) + (e1.x + e1.y) + (e1.z + e1.w);
    sm[tid] = z;
    __syncthreads();
    for (int off = 256; off > 0; off >>= 1) {
        if (tid < off) sm[tid] += sm[tid + off];
        __syncthreads();
    }
    float inv = 1.f / sm[0];

    float4* w4 = (float4*)(wout + (size_t)b * NT);
    e0.x *= inv; e0.y *= inv; e0.z *= inv; e0.w *= inv;
    e1.x *= inv; e1.y *= inv; e1.z *= inv; e1.w *= inv;
    w4[tid]       = e0;
    w4[tid + 512] = e1;
}

// ---------------------------------------------------------------------------
// Kernel 4: context partial sums from fp16 enc copy (halved DRAM traffic).
//   grid (NB, TCH), 64 threads; each thread owns 8 columns (16B loads).
// ---------------------------------------------------------------------------
__global__ void k_ctx_part(const float* __restrict__ w) {
    const int b   = blockIdx.x;
    const int tc  = blockIdx.y;
    const int tid = threadIdx.x;   // 0..63
    const int TLEN = NT / TCH;     // 64
    const float*  wp = w + (size_t)b * NT + (size_t)tc * TLEN;
    const __half* ep = g_enc16 + ((size_t)b * NT + (size_t)tc * TLEN) * HE;

    float acc[8];
#pragma unroll
    for (int j = 0; j < 8; j++) acc[j] = 0.f;

#pragma unroll 4
    for (int t = 0; t < TLEN; ++t) {
        float wt = wp[t];
        uint4 hv = *(const uint4*)(ep + (size_t)t * HE + tid * 8);
        const __half2* hp = (const __half2*)&hv;
#pragma unroll
        for (int j = 0; j < 4; j++) {
            float2 f = __half22float2(hp[j]);
            acc[2 * j + 0] = fmaf(wt, f.x, acc[2 * j + 0]);
            acc[2 * j + 1] = fmaf(wt, f.y, acc[2 * j + 1]);
        }
    }
    float* dst = g_ctx_part + ((size_t)b * TCH + tc) * HE + tid * 8;
    *(float4*)dst       = make_float4(acc[0], acc[1], acc[2], acc[3]);
    *(float4*)(dst + 4) = make_float4(acc[4], acc[5], acc[6], acc[7]);
}

// ---------------------------------------------------------------------------
// Kernel 5: reduce partials -> context output.
// ---------------------------------------------------------------------------
__global__ void k_ctx_reduce(float* __restrict__ ctx) {
    int idx = blockIdx.x * blockDim.x + threadIdx.x;
    int b = idx / HE;
    int e = idx % HE;
    float s = 0.f;
#pragma unroll
    for (int c = 0; c < TCH; c++)
        s += g_ctx_part[((size_t)b * TCH + c) * HE + e];
    ctx[idx] = s;
}

// ---------------------------------------------------------------------------
extern "C" void kernel_launch(void* const* d_in, const int* in_sizes, int n_in,
                              void* d_out, int out_size) {
    const float* dec = (const float*)d_in[0];  // (B, H_dec)
    const float* enc = (const float*)d_in[1];  // (B, T, H_enc)
    const float* We  = (const float*)d_in[2];  // (A, H_enc)
    const float* Wd  = (const float*)d_in[3];  // (A, H_dec)
    const float* v   = (const float*)d_in[4];  // (1, A)

    float* out = (float*)d_out;
    float* ctx = out;              // context: B*HE
    float* wts = out + NB * HE;    // attn_weights: B*NT

    cudaFuncSetAttribute(k_scores, cudaFuncAttributeMaxDynamicSharedMemorySize,
                         SMEM_BYTES);

    k_wprep<<<NKCH, BN>>>(We);
    k_dec_proj<<<NB, NA>>>(dec, Wd);

    dim3 g2(NT / BM, NB);
    k_scores<<<g2, THREADS, SMEM_BYTES>>>(enc, v);

    k_softmax<<<NB, 512>>>(wts);

    dim3 g4(NB, TCH);
    k_ctx_part<<<g4, 64>>>(wts);

    k_ctx_reduce<<<(NB * HE) / 256, 256>>>(ctx);
}

// round 14
// speedup vs baseline: 1.2759x; 1.0072x over previous
#include <cuda_runtime.h>
#include <cuda_fp16.h>
#include <math.h>
#include <stdint.h>

#define NB 64
#define NT 4096
#define HE 512
#define HD 512
#define NA 256
#define TCH 64

// ---- scores GEMM tiling ----
#define BM 128
#define BN 256
#define BK 32
#define NKCH (HE / BK)        // 16
#define NPAIR (NKCH / 2)      // 8
#define THREADS 512
#define STAGES 6

// smem tile rows: 64B data + 16B pad = 80B stride
#define ROWB 80
#define ASZ (BM * ROWB)            // 10240
#define BSZ (BN * ROWB)            // 20480
#define BUFSZ (ASZ + BSZ)          // 30720
#define SCAL (STAGES * BUFSZ)      // 184320
#define SMEM_BYTES (SCAL + 1024 + 1024 + 2048)   // 188416

// ---------------- static device scratch (allocation-free) ----------------
__device__ float g_dec_proj[NB * NA];
__device__ float g_scores[NB * NT];
__device__ float g_ctx_part[NB * TCH * HE];
// fp16 copy of encoder_outputs, written by k_scores, read by k_ctx_part
__device__ __half g_enc16[(size_t)NB * NT * HE];
// prepacked W_enc fp16: [kchunk 16][n 256][k 32] (64B rows)
__device__ unsigned char g_Bs[NKCH * BN * 64];

// ---------------- helpers ----------------
__device__ __forceinline__ unsigned smem_u32(const void* p) {
    unsigned r;
    asm("{ .reg .u64 t; cvta.to.shared.u64 t, %1; cvt.u32.u64 %0, t; }"
        : "=r"(r) : "l"(p));
    return r;
}
__device__ __forceinline__ void cpasync16(unsigned dst, const void* src) {
    asm volatile("cp.async.cg.shared.global [%0], [%1], 16;"
                 :: "r"(dst), "l"(__cvta_generic_to_global(src)) : "memory");
}
__device__ __forceinline__ unsigned pack_h2(float a, float b) {
    __half2 h = __floats2half2_rn(a, b);
    return *reinterpret_cast<unsigned*>(&h);
}

#define LDSM4(r, addr)                                                        \
    asm volatile("ldmatrix.sync.aligned.m8n8.x4.shared.b16 {%0,%1,%2,%3}, [%4];" \
                 : "=r"((r)[0]), "=r"((r)[1]), "=r"((r)[2]), "=r"((r)[3])     \
                 : "r"(addr))

#define MMA(d, a, b0, b1)                                                     \
    asm volatile(                                                             \
        "mma.sync.aligned.m16n8k16.row.col.f32.f16.f16.f32 "                  \
        "{%0,%1,%2,%3}, {%4,%5,%6,%7}, {%8,%9}, {%0,%1,%2,%3};"               \
        : "+f"((d)[0]), "+f"((d)[1]), "+f"((d)[2]), "+f"((d)[3])              \
        : "r"((a)[0]), "r"((a)[1]), "r"((a)[2]), "r"((a)[3]), "r"(b0), "r"(b1))

// HW tanh approximation (sm_75+, single MUFU op)
__device__ __forceinline__ float ftanh(float x) {
    float r;
    asm("tanh.approx.f32 %0, %1;" : "=f"(r) : "f"(x));
    return r;
}

// ---------------------------------------------------------------------------
// Kernel 0: merged prep. Blocks 0..15: prepack W_enc chunk c=bid.
//           Blocks 16..79: dec_proj for b = bid-16.
// ---------------------------------------------------------------------------
__global__ void k_prep(const float* __restrict__ We,
                       const float* __restrict__ dec,
                       const float* __restrict__ Wd) {
    if (blockIdx.x < NKCH) {
        int c = blockIdx.x;
        int n = threadIdx.x;     // 0..255
        const float* src = We + (size_t)n * HE + c * BK;
        unsigned hbuf[16];
#pragma unroll
        for (int q = 0; q < 8; q++) {
            float4 f = *(const float4*)(src + q * 4);
            hbuf[q * 2 + 0] = pack_h2(f.x, f.y);
            hbuf[q * 2 + 1] = pack_h2(f.z, f.w);
        }
        unsigned char* dsth = g_Bs + ((size_t)c * BN + n) * 64;
#pragma unroll
        for (int q = 0; q < 4; q++)
            ((uint4*)dsth)[q] = make_uint4(hbuf[q*4], hbuf[q*4+1],
                                           hbuf[q*4+2], hbuf[q*4+3]);
    } else {
        int b = blockIdx.x - NKCH;
        int a = threadIdx.x;
        const float4* dp = (const float4*)(dec + (size_t)b * HD);
        const float4* wp = (const float4*)(Wd + (size_t)a * HD);
        float s = 0.f;
#pragma unroll 8
        for (int k = 0; k < HD / 4; ++k) {
            float4 d4 = dp[k];
            float4 w4 = wp[k];
            s += d4.x * w4.x + d4.y * w4.y + d4.z * w4.z + d4.w * w4.w;
        }
        g_dec_proj[b * NA + a] = s;
    }
}

// ---------------------------------------------------------------------------
// Kernel 2: fused scores, mma.sync fp16, 6-stage cp.async ring processed in
//   chunk PAIRS (one barrier per 2 chunks). grid (NT/128, NB), 512 threads,
//   16 warps (4 M x 4 N). Data layout identical to the proven R9 config.
// ---------------------------------------------------------------------------
__global__ __launch_bounds__(THREADS, 1)
void k_scores(const float* __restrict__ enc, const float* __restrict__ v) {
    extern __shared__ __align__(128) unsigned char smp[];
    const unsigned sb = smem_u32(smp);

    const int tid = threadIdx.x;
    const int wid = tid >> 5;
    const int l   = tid & 31;
    const int wm  = wid & 3;   // M blocks of 32
    const int wn  = wid >> 2;  // N blocks of 64
    const int b   = blockIdx.y;
    const int t0  = blockIdx.x * BM;

    float* sdec = (float*)(smp + SCAL);
    float* sv   = (float*)(smp + SCAL + 1024);
    float* srow = (float*)(smp + SCAL + 2048);   // [128][4]
    if (tid < NA) {
        sdec[tid] = g_dec_proj[b * NA + tid];
        sv[tid]   = v[tid];
    }

    const float* Abase = enc + ((size_t)b * NT + t0) * HE;
    const int arow = tid >> 2;   // 0..127
    const int aseg = tid & 3;    // 8 floats each

    auto ldA = [&](int c, float4& v0, float4& v1) {
        const float* p = Abase + (size_t)arow * HE + c * BK + aseg * 8;
        v0 = *(const float4*)p;
        v1 = *(const float4*)(p + 4);
    };
    auto stA = [&](int st, int c, float4 v0, float4 v1) {
        unsigned off = st * BUFSZ + arow * ROWB + aseg * 16;
        uint4 h = make_uint4(pack_h2(v0.x, v0.y), pack_h2(v0.z, v0.w),
                             pack_h2(v1.x, v1.y), pack_h2(v1.z, v1.w));
        *(uint4*)(smp + off) = h;
        // side-write fp16 enc copy for the context kernel
        *(uint4*)(g_enc16 + ((size_t)b * NT + t0 + arow) * HE + c * BK + aseg * 8) = h;
    };
    auto ldB = [&](int c, int st) {
#pragma unroll
        for (int it = 0; it < 2; it++) {
            int i   = tid + it * THREADS;   // 0..1023
            int row = i >> 2;
            int cc  = i & 3;
            unsigned dst = sb + st * BUFSZ + ASZ + row * ROWB + cc * 16;
            const unsigned char* src = g_Bs + ((size_t)c * BN + row) * 64 + cc * 16;
            cpasync16(dst, src);
        }
        asm volatile("cp.async.commit_group;" ::: "memory");
    };

    float acc[2][8][4];
#pragma unroll
    for (int i = 0; i < 2; i++)
#pragma unroll
        for (int j = 0; j < 8; j++)
#pragma unroll
            for (int k = 0; k < 4; k++) acc[i][j][k] = 0.f;

    const unsigned a_lane = (wm * 32 + (l & 15)) * ROWB + ((l >> 4) << 4);
    const unsigned b_lane = (wn * 64 + ((l >> 4) & 1) * 8 + (l & 7)) * ROWB
                          + (((l >> 3) & 1) << 4);

    // one chunk's compute (stage st), R9-style frag-pipelined body
    auto compute = [&](int st) {
        const unsigned sA = sb + st * BUFSZ;
        const unsigned sB = sb + st * BUFSZ + ASZ;
        unsigned ah[2][2][4];
        unsigned bh[2][4];
        LDSM4(ah[0][0], sA + a_lane);
        LDSM4(ah[0][1], sA + a_lane + 16 * ROWB);
#pragma unroll
        for (int k16 = 0; k16 < 2; k16++) {
            const unsigned boff = b_lane + k16 * 32;
            LDSM4(bh[0], sB + boff);
            if (k16 == 0) {
                LDSM4(ah[1][0], sA + a_lane + 32);
                LDSM4(ah[1][1], sA + a_lane + 32 + 16 * ROWB);
            }
#pragma unroll
            for (int np = 0; np < 4; np++) {
                if (np < 3)
                    LDSM4(bh[(np + 1) & 1], sB + boff + (np + 1) * (16 * ROWB));
                const unsigned* bc = bh[np & 1];
                MMA(acc[0][2 * np],     ah[k16][0], bc[0], bc[1]);
                MMA(acc[0][2 * np + 1], ah[k16][0], bc[2], bc[3]);
                MMA(acc[1][2 * np],     ah[k16][1], bc[0], bc[1]);
                MMA(acc[1][2 * np + 1], ah[k16][1], bc[2], bc[3]);
            }
        }
    };

    // ---- prologue: chunks 0..3 into stages 0..3 (B async, A direct) ----
    ldB(0, 0); ldB(1, 1); ldB(2, 2); ldB(3, 3);
#pragma unroll
    for (int c = 0; c < 4; c++) {
        float4 a0, a1;
        ldA(c, a0, a1);
        stA(c, c, a0, a1);
    }
    asm volatile("cp.async.wait_group 2;" ::: "memory");   // 0,1 done; 2,3 in flight
    __syncthreads();

    // ---- main loop: one barrier per pair of chunks ----
    for (int p = 0; p < NPAIR; p++) {
        const int c0 = 2 * p;
        const bool more = (p + 2 < NPAIR);    // chunks c0+4, c0+5 exist

        float4 wa0, wa1, wb0, wb1;
        if (more) {
            ldA(c0 + 4, wa0, wa1);
            ldA(c0 + 5, wb0, wb1);
            ldB(c0 + 4, (c0 + 4) % STAGES);
            ldB(c0 + 5, (c0 + 5) % STAGES);
        }

        compute(c0 % STAGES);
        compute((c0 + 1) % STAGES);

        if (more) {
            stA((c0 + 4) % STAGES, c0 + 4, wa0, wa1);
            stA((c0 + 5) % STAGES, c0 + 5, wb0, wb1);
            // ensure next pair's groups (c0+2, c0+3) are done; leave the two
            // just-issued (c0+4, c0+5) outstanding
            asm volatile("cp.async.wait_group 2;" ::: "memory");
        } else if (p + 1 < NPAIR) {
            asm volatile("cp.async.wait_group 0;" ::: "memory");
        }
        __syncthreads();
    }

    // epilogue: tanh(acc + dec) * v, reduce over 256 cols
    const int gid = l >> 2;
    const int tig = l & 3;
    float rs[2][2] = {{0.f, 0.f}, {0.f, 0.f}};
#pragma unroll
    for (int mt = 0; mt < 2; mt++) {
#pragma unroll
        for (int nt = 0; nt < 8; nt++) {
            int col0 = wn * 64 + nt * 8 + tig * 2;
            float d0 = sdec[col0], d1 = sdec[col0 + 1];
            float v0 = sv[col0],   v1 = sv[col0 + 1];
            rs[mt][0] += ftanh(acc[mt][nt][0] + d0) * v0;
            rs[mt][0] += ftanh(acc[mt][nt][1] + d1) * v1;
            rs[mt][1] += ftanh(acc[mt][nt][2] + d0) * v0;
            rs[mt][1] += ftanh(acc[mt][nt][3] + d1) * v1;
        }
    }
#pragma unroll
    for (int mt = 0; mt < 2; mt++)
#pragma unroll
        for (int rh = 0; rh < 2; rh++) {
            float s = rs[mt][rh];
            s += __shfl_xor_sync(0xFFFFFFFFu, s, 1);
            s += __shfl_xor_sync(0xFFFFFFFFu, s, 2);
            if (tig == 0) {
                int row = wm * 32 + mt * 16 + rh * 8 + gid;
                srow[row * 4 + wn] = s;
            }
        }
    __syncthreads();
    if (tid < BM) {
        float s = srow[tid * 4 + 0] + srow[tid * 4 + 1]
                + srow[tid * 4 + 2] + srow[tid * 4 + 3];
        g_scores[(size_t)b * NT + t0 + tid] = s;
    }
}

// ---------------------------------------------------------------------------
// Kernel 3: softmax over T per batch (512 threads, float4)
// ---------------------------------------------------------------------------
__global__ void k_softmax(float* __restrict__ wout) {
    const int b = blockIdx.x;
    const int tid = threadIdx.x;   // 0..511
    __shared__ float sm[512];
    const float4* s4 = (const float4*)(g_scores + (size_t)b * NT);

    float4 x0 = s4[tid];
    float4 x1 = s4[tid + 512];
    float m = fmaxf(fmaxf(fmaxf(x0.x, x0.y), fmaxf(x0.z, x0.w)),
                    fmaxf(fmaxf(x1.x, x1.y), fmaxf(x1.z, x1.w)));
    sm[tid] = m;
    __syncthreads();
    for (int off = 256; off > 0; off >>= 1) {
        if (tid < off) sm[tid] = fmaxf(sm[tid], sm[tid + off]);
        __syncthreads();
    }
    m = sm[0];
    __syncthreads();

    float4 e0, e1;
    e0.x = expf(x0.x - m); e0.y = expf(x0.y - m);
    e0.z = expf(x0.z - m); e0.w = expf(x0.w - m);
    e1.x = expf(x1.x - m); e1.y = expf(x1.y - m);
    e1.z = expf(x1.z - m); e1.w = expf(x1.w - m);
    float z = (e0.x + e0.y) + (e0.z + e0.w) + (e1.x + e1.y) + (e1.z + e1.w);
    sm[tid] = z;
    __syncthreads();
    for (int off = 256; off > 0; off >>= 1) {
        if (tid < off) sm[tid] += sm[tid + off];
        __syncthreads();
    }
    float inv = 1.f / sm[0];

    float4* w4 = (float4*)(wout + (size_t)b * NT);
    e0.x *= inv; e0.y *= inv; e0.z *= inv; e0.w *= inv;
    e1.x *= inv; e1.y *= inv; e1.z *= inv; e1.w *= inv;
    w4[tid]       = e0;
    w4[tid + 512] = e1;
}

// ---------------------------------------------------------------------------
// Kernel 4: context partial sums from fp16 enc copy.
//   grid (NB, TCH), 64 threads; each thread owns 8 columns (16B loads).
// ---------------------------------------------------------------------------
__global__ void k_ctx_part(const float* __restrict__ w) {
    const int b   = blockIdx.x;
    const int tc  = blockIdx.y;
    const int tid = threadIdx.x;   // 0..63
    const int TLEN = NT / TCH;     // 64
    const float*  wp = w + (size_t)b * NT + (size_t)tc * TLEN;
    const __half* ep = g_enc16 + ((size_t)b * NT + (size_t)tc * TLEN) * HE;

    float acc[8];
#pragma unroll
    for (int j = 0; j < 8; j++) acc[j] = 0.f;

#pragma unroll 4
    for (int t = 0; t < TLEN; ++t) {
        float wt = wp[t];
        uint4 hv = *(const uint4*)(ep + (size_t)t * HE + tid * 8);
        const __half2* hp = (const __half2*)&hv;
#pragma unroll
        for (int j = 0; j < 4; j++) {
            float2 f = __half22float2(hp[j]);
            acc[2 * j + 0] = fmaf(wt, f.x, acc[2 * j + 0]);
            acc[2 * j + 1] = fmaf(wt, f.y, acc[2 * j + 1]);
        }
    }
    float* dst = g_ctx_part + ((size_t)b * TCH + tc) * HE + tid * 8;
    *(float4*)dst       = make_float4(acc[0], acc[1], acc[2], acc[3]);
    *(float4*)(dst + 4) = make_float4(acc[4], acc[5], acc[6], acc[7]);
}

// ---------------------------------------------------------------------------
// Kernel 5: reduce partials -> context output.
// ---------------------------------------------------------------------------
__global__ void k_ctx_reduce(float* __restrict__ ctx) {
    int idx = blockIdx.x * blockDim.x + threadIdx.x;
    int b = idx / HE;
    int e = idx % HE;
    float s = 0.f;
#pragma unroll
    for (int c = 0; c < TCH; c++)
        s += g_ctx_part[((size_t)b * TCH + c) * HE + e];
    ctx[idx] = s;
}

// ---------------------------------------------------------------------------
extern "C" void kernel_launch(void* const* d_in, const int* in_sizes, int n_in,
                              void* d_out, int out_size) {
    const float* dec = (const float*)d_in[0];  // (B, H_dec)
    const float* enc = (const float*)d_in[1];  // (B, T, H_enc)
    const float* We  = (const float*)d_in[2];  // (A, H_enc)
    const float* Wd  = (const float*)d_in[3];  // (A, H_dec)
    const float* v   = (const float*)d_in[4];  // (1, A)

    float* out = (float*)d_out;
    float* ctx = out;              // context: B*HE
    float* wts = out + NB * HE;    // attn_weights: B*NT

    cudaFuncSetAttribute(k_scores, cudaFuncAttributeMaxDynamicSharedMemorySize,
                         SMEM_BYTES);

    k_prep<<<NKCH + NB, 256>>>(We, dec, Wd);

    dim3 g2(NT / BM, NB);
    k_scores<<<g2, THREADS, SMEM_BYTES>>>(enc, v);

    k_softmax<<<NB, 512>>>(wts);

    dim3 g4(NB, TCH);
    k_ctx_part<<<g4, 64>>>(wts);

    k_ctx_reduce<<<(NB * HE) / 256, 256>>>(ctx);
}